// round 15
// baseline (speedup 1.0000x reference)
#include <cuda_runtime.h>
#include <math.h>

#define NRAYS 8192
#define TS 256
#define NBLK 4736
#define NTH 128

typedef unsigned long long ull;

__device__ __forceinline__ ull fma2(ull a, ull b, ull c) {
    ull d;
    asm("fma.rn.f32x2 %0, %1, %2, %3;" : "=l"(d) : "l"(a), "l"(b), "l"(c));
    return d;
}
__device__ __forceinline__ ull pack2(float lo, float hi) {
    ull d;
    asm("mov.b64 %0, {%1, %2};" : "=l"(d) : "f"(lo), "f"(hi));
    return d;
}
__device__ __forceinline__ float2 unpack2(ull v) {
    float2 r;
    asm("mov.b64 {%0, %1}, %2;" : "=f"(r.x), "=f"(r.y) : "l"(v));
    return r;
}
__device__ __forceinline__ float frcp(float x) {
    float r;
    asm("rcp.approx.f32 %0, %1;" : "=f"(r) : "f"(x));
    return r;
}
__device__ __forceinline__ float fsig(float x) {
    return frcp(1.f + __expf(-x));
}

// ---- shared weight buffer layout (float offsets, all 16B-aligned bases) ----
#define O_WD1T 0      // [64][4]  (wx,wy,wz,bias)
#define O_WD2P 256    // [64][16] cols rotated by 1: slot j = orig col (j+1)&15
#define O_BD2P 1280   // [16]     rotated bd2
#define O_WC1G 1296   // [64][16] geo weights for slots d1..d15, slot15 = 0
#define O_WC2  2320   // [64][4]  64->3 padded
#define O_BC2  2576   // [4]
#define O_WK1T 2580   // [64][16] clip l1 weights (slots d1..d15, sigma)
#define O_BK1P 3604   // [64][2]  {bk1, 0} pairs
#define O_WK2  3732   // [64][32]
#define O_BK2  5780   // [32]
#define SW_TOTAL 5812

// output layout: image[N,3] | depth[N] | depth_var[N] | coords[N,3] | rgbs[N,T,3] | clip[N,32]
#define OUT_IMG 0
#define OUT_DEP (3*NRAYS)
#define OUT_VAR (4*NRAYS)
#define OUT_CRD (5*NRAYS)
#define OUT_RGB (8*NRAYS)
#define OUT_CLP (8L*NRAYS + 3L*NRAYS*TS)

__global__ void __launch_bounds__(128) nerf_kernel(
    const float* __restrict__ rays_o,
    const float* __restrict__ rays_d,
    const float* __restrict__ dnorm,
    const float* __restrict__ Wd1, const float* __restrict__ bd1,
    const float* __restrict__ Wd2, const float* __restrict__ bd2,
    const float* __restrict__ Wc1, const float* __restrict__ bc1,
    const float* __restrict__ Wc2, const float* __restrict__ bc2,
    const float* __restrict__ Wk1, const float* __restrict__ bk1,
    const float* __restrict__ Wk2, const float* __restrict__ bk2,
    float* __restrict__ out)
{
    __shared__ __align__(16) float sw[SW_TOTAL];
    __shared__ __align__(16) float sab[2][256];  // ping-pong per-ray {A,A,B,B} density L1 lin.
    __shared__ __align__(16) float dircp[128];   // {dirc[h], 0} pairs (per ray)
    __shared__ float wp0[4], wp1[4];
    __shared__ float red[4][12];
    __shared__ float finals[12];
    __shared__ __align__(16) float gred[4][64];
    __shared__ __align__(16) float gsm[64];

    const int tid = threadIdx.x;
    const int lane = tid & 31;
    const int wid = tid >> 5;

    // ---- stage weights into smem ----
    for (int i = tid; i < 256; i += NTH) { int h = i >> 2, c = i & 3; sw[O_WD1T + i] = (c < 3) ? Wd1[c * 64 + h] : bd1[h]; }
    for (int i = tid; i < 1024; i += NTH) { int j = i & 15; sw[O_WD2P + i] = Wd2[(i & ~15) + ((j + 1) & 15)]; }
    for (int i = tid; i < 16; i += NTH) sw[O_BD2P + i] = bd2[(i + 1) & 15];
    for (int i = tid; i < 1024; i += NTH) { int h = i >> 4, c = i & 15; sw[O_WC1G + i] = (c < 15) ? Wc1[(3 + c) * 64 + h] : 0.f; }
    for (int i = tid; i < 256; i += NTH) { int h = i >> 2, k = i & 3; sw[O_WC2 + i] = (k < 3) ? Wc2[h * 3 + k] : 0.f; }
    if (tid < 4) sw[O_BC2 + tid] = (tid < 3) ? bc2[tid] : 0.f;
    for (int i = tid; i < 1024; i += NTH) { int h = i >> 4, c = i & 15; sw[O_WK1T + i] = Wk1[c * 64 + h]; }
    for (int i = tid; i < 128; i += NTH) sw[O_BK1P + i] = (i & 1) ? 0.f : bk1[i >> 1];
    for (int i = tid; i < 2048; i += NTH) sw[O_WK2 + i] = Wk2[i];
    for (int i = tid; i < 32; i += NTH) sw[O_BK2 + i] = bk2[i];
    __syncthreads();

    // ---- pre-stage density L1 linearization for the first ray ----
    if (tid < 64 && blockIdx.x < NRAYS) {
        const int r0 = blockIdx.x;
        const float nox = rays_o[r0 * 3 + 0], noy = rays_o[r0 * 3 + 1], noz = rays_o[r0 * 3 + 2];
        const float ndx = rays_d[r0 * 3 + 0], ndy = rays_d[r0 * 3 + 1], ndz = rays_d[r0 * 3 + 2];
        const float4 w1 = *reinterpret_cast<const float4*>(&sw[O_WD1T + 4 * tid]);
        const float A = fmaf(w1.x, nox, fmaf(w1.y, noy, fmaf(w1.z, noz, w1.w)));
        const float B = fmaf(w1.x, ndx, fmaf(w1.y, ndy, w1.z * ndz));
        float4 v4; v4.x = A; v4.y = A; v4.z = B; v4.w = B;
        *reinterpret_cast<float4*>(&sab[0][4 * tid]) = v4;
    }
    __syncthreads();

    int par = 0;
    for (int ray = blockIdx.x; ray < NRAYS; ray += gridDim.x, par ^= 1) {
        // ---- ray setup ----
        const float ox = rays_o[ray * 3 + 0], oy = rays_o[ray * 3 + 1], oz = rays_o[ray * 3 + 2];
        const float dx = rays_d[ray * 3 + 0], dy = rays_d[ray * 3 + 1], dz = rays_d[ray * 3 + 2];

        // per-ray direction contribution to color layer-1 (incl. bias), stored as {v,0} pairs
        // (scan __syncthreads below orders these writes before the color-loop reads)
        if (tid < 64) {
            dircp[2 * tid] = bc1[tid] + dx * Wc1[tid] + dy * Wc1[64 + tid] + dz * Wc1[128 + tid];
            dircp[2 * tid + 1] = 0.f;
        }

        const float ix = frcp(dx), iy = frcp(dy), iz = frcp(dz);
        float t1, t2;
        t1 = (-1.f - ox) * ix; t2 = (1.f - ox) * ix;
        float mnx = fminf(t1, t2), mxx = fmaxf(t1, t2);
        t1 = (-1.f - oy) * iy; t2 = (1.f - oy) * iy;
        float mny = fminf(t1, t2), mxy = fmaxf(t1, t2);
        t1 = (-1.f - oz) * iz; t2 = (1.f - oz) * iz;
        float mnz = fminf(t1, t2), mxz = fmaxf(t1, t2);
        const float nearv = fmaxf(fmaxf(fmaxf(mnx, mny), mnz), 0.2f);
        const float farv  = fmaxf(fminf(fminf(mxx, mxy), mxz), nearv + 0.0001f);
        const float span = farv - nearv;

        const float tstep = span * (1.f / (TS - 1));
        const float zv0 = nearv + tstep * (float)tid;
        const float zv1 = nearv + tstep * (float)(tid + 128);
        const ull zp = pack2(zv0, zv1);

        // ---- density MLP: linearized L1 (1 FMA2 per h) -> relu -> 16 (permuted, packed) ----
        // accumulator pairs: (d1,d2),(d3,d4),...,(d13,d14),(d15,d0)
        ull acc0[8], acc1[8];
        {
            const ull* bp = reinterpret_cast<const ull*>(&sw[O_BD2P]);
            #pragma unroll
            for (int j = 0; j < 8; j++) { acc0[j] = bp[j]; acc1[j] = bp[j]; }
        }
        {
            const float* sabp = sab[par];
            #pragma unroll 4
            for (int h = 0; h < 64; h++) {
                const ulonglong2 ab = *reinterpret_cast<const ulonglong2*>(&sabp[4 * h]);
                const float2 pp = unpack2(fma2(zp, ab.y, ab.x));   // {A+B*zv0, A+B*zv1}
                const float p0 = fmaxf(pp.x, 0.f);
                const float p1 = fmaxf(pp.y, 0.f);
                const ull p0b = pack2(p0, p0);
                const ull p1b = pack2(p1, p1);
                const ulonglong2* wr = reinterpret_cast<const ulonglong2*>(&sw[O_WD2P + h * 16]);
                #pragma unroll
                for (int q = 0; q < 4; q++) {
                    const ulonglong2 w = wr[q];
                    acc0[2 * q + 0] = fma2(p0b, w.x, acc0[2 * q + 0]);
                    acc0[2 * q + 1] = fma2(p0b, w.y, acc0[2 * q + 1]);
                    acc1[2 * q + 0] = fma2(p1b, w.x, acc1[2 * q + 0]);
                    acc1[2 * q + 1] = fma2(p1b, w.y, acc1[2 * q + 1]);
                }
            }
        }
        const float2 t7a = unpack2(acc0[7]);   // (d15, d0)
        const float2 t7b = unpack2(acc1[7]);
        const float sigma0 = __expf(t7a.y);
        const float sigma1 = __expf(t7b.y);

        // ---- alpha + two-level transmittance scan over 256 samples ----
        const float delta1 = (tid < 127) ? tstep : span * (1.f / TS);
        const float alpha0 = 1.f - __expf(-tstep * sigma0);
        const float alpha1 = 1.f - __expf(-delta1 * sigma1);
        float v0 = 1.f - alpha0 + 1e-15f;
        float v1 = 1.f - alpha1 + 1e-15f;
        #pragma unroll
        for (int off = 1; off < 32; off <<= 1) {
            const float n0 = __shfl_up_sync(0xffffffffu, v0, off);
            const float n1 = __shfl_up_sync(0xffffffffu, v1, off);
            if (lane >= off) { v0 *= n0; v1 *= n1; }
        }
        if (lane == 31) { wp0[wid] = v0; wp1[wid] = v1; }
        __syncthreads();
        float pre0p = 1.f, pre1p;
        {
            #pragma unroll
            for (int i = 0; i < 4; i++) if (i < wid) pre0p *= wp0[i];
            const float all0 = wp0[0] * wp0[1] * wp0[2] * wp0[3];
            pre1p = all0;
            #pragma unroll
            for (int i = 0; i < 4; i++) if (i < wid) pre1p *= wp1[i];
        }
        float e0 = __shfl_up_sync(0xffffffffu, v0, 1);
        float e1 = __shfl_up_sync(0xffffffffu, v1, 1);
        if (lane == 0) { e0 = 1.f; e1 = 1.f; }
        float w0v = alpha0 * (pre0p * e0);
        float w1v = alpha1 * (pre1p * e1);
        const bool m0 = (w0v > 0.0001f);
        const bool m1 = (w1v > 0.0001f);
        if (!m0) w0v = 0.f;
        if (!m1) w1v = 0.f;

        // ---- color MLP: [dir(hoisted), geo(15)] -> 64 (relu) -> 3 (sigmoid) ----
        float c00 = sw[O_BC2 + 0], c01 = sw[O_BC2 + 1], c02 = sw[O_BC2 + 2];
        float c10 = c00, c11 = c01, c12 = c02;
        #pragma unroll 2
        for (int h = 0; h < 64; h++) {
            ull a0 = *reinterpret_cast<const ull*>(&dircp[2 * h]);
            ull a1 = a0;
            const ulonglong2* wr = reinterpret_cast<const ulonglong2*>(&sw[O_WC1G + h * 16]);
            #pragma unroll
            for (int q = 0; q < 4; q++) {
                const ulonglong2 w = wr[q];
                a0 = fma2(acc0[2 * q + 0], w.x, a0);
                a0 = fma2(acc0[2 * q + 1], w.y, a0);
                a1 = fma2(acc1[2 * q + 0], w.x, a1);
                a1 = fma2(acc1[2 * q + 1], w.y, a1);
            }
            const float2 s0 = unpack2(a0);
            const float2 s1 = unpack2(a1);
            const float hv0 = fmaxf(s0.x + s0.y, 0.f);
            const float hv1 = fmaxf(s1.x + s1.y, 0.f);
            const float4 w2 = *reinterpret_cast<const float4*>(&sw[O_WC2 + h * 4]);
            c00 = fmaf(hv0, w2.x, c00); c01 = fmaf(hv0, w2.y, c01); c02 = fmaf(hv0, w2.z, c02);
            c10 = fmaf(hv1, w2.x, c10); c11 = fmaf(hv1, w2.y, c11); c12 = fmaf(hv1, w2.z, c12);
        }
        float r00 = fsig(c00), r01 = fsig(c01), r02 = fsig(c02);
        float r10 = fsig(c10), r11 = fsig(c11), r12 = fsig(c12);
        if (!m0) { r00 = 0.f; r01 = 0.f; r02 = 0.f; }
        if (!m1) { r10 = 0.f; r11 = 0.f; r12 = 0.f; }
        {
            const long b0 = OUT_RGB + ((long)ray * TS + tid) * 3;
            out[b0 + 0] = r00; out[b0 + 1] = r01; out[b0 + 2] = r02;
            const long b1 = OUT_RGB + ((long)ray * TS + tid + 128) * 3;
            out[b1 + 0] = r10; out[b1 + 1] = r11; out[b1 + 2] = r12;
        }

        // ---- 9-quantity block reduction (positions computed here) ----
        {
            const float px0 = fminf(fmaxf(fmaf(dx, zv0, ox), -1.f), 1.f);
            const float py0 = fminf(fmaxf(fmaf(dy, zv0, oy), -1.f), 1.f);
            const float pz0 = fminf(fmaxf(fmaf(dz, zv0, oz), -1.f), 1.f);
            const float px1 = fminf(fmaxf(fmaf(dx, zv1, ox), -1.f), 1.f);
            const float py1 = fminf(fmaxf(fmaf(dy, zv1, oy), -1.f), 1.f);
            const float pz1 = fminf(fmaxf(fmaf(dz, zv1, oz), -1.f), 1.f);
            float vals[9];
            vals[0] = w0v + w1v;
            vals[1] = w0v * zv0 + w1v * zv1;
            vals[2] = w0v * zv0 * zv0 + w1v * zv1 * zv1;
            vals[3] = w0v * px0 + w1v * px1;
            vals[4] = w0v * py0 + w1v * py1;
            vals[5] = w0v * pz0 + w1v * pz1;
            vals[6] = w0v * r00 + w1v * r10;
            vals[7] = w0v * r01 + w1v * r11;
            vals[8] = w0v * r02 + w1v * r12;
            #pragma unroll
            for (int q = 0; q < 9; q++) {
                float x = vals[q];
                #pragma unroll
                for (int off = 16; off > 0; off >>= 1) x += __shfl_xor_sync(0xffffffffu, x, off);
                vals[q] = x;
            }
            if (lane == 0) {
                #pragma unroll
                for (int q = 0; q < 9; q++) red[wid][q] = vals[q];
            }
        }

        // ---- clip hidden layer: [geo(15), sigma] -> 64 (relu), weighted-reduced over t ----
        // butterfly transpose-reduction: 16 h's per pass, 4 passes
        const ull kp0 = pack2(t7a.x, sigma0);   // (d15, sigma)
        const ull kp1 = pack2(t7b.x, sigma1);
        #pragma unroll 1
        for (int base = 0; base < 64; base += 16) {
            float gq[16];
            #pragma unroll
            for (int j = 0; j < 16; j++) {
                const int h = base + j;
                ull a0 = *reinterpret_cast<const ull*>(&sw[O_BK1P + 2 * h]);
                ull a1 = a0;
                const ulonglong2* wr = reinterpret_cast<const ulonglong2*>(&sw[O_WK1T + h * 16]);
                #pragma unroll
                for (int q = 0; q < 3; q++) {
                    const ulonglong2 w = wr[q];
                    a0 = fma2(acc0[2 * q + 0], w.x, a0);
                    a0 = fma2(acc0[2 * q + 1], w.y, a0);
                    a1 = fma2(acc1[2 * q + 0], w.x, a1);
                    a1 = fma2(acc1[2 * q + 1], w.y, a1);
                }
                const ulonglong2 w3 = wr[3];
                a0 = fma2(acc0[6], w3.x, a0);
                a1 = fma2(acc1[6], w3.x, a1);
                a0 = fma2(kp0, w3.y, a0);
                a1 = fma2(kp1, w3.y, a1);
                const float2 s0 = unpack2(a0);
                const float2 s1 = unpack2(a1);
                gq[j] = w0v * fmaxf(s0.x + s0.y, 0.f) + w1v * fmaxf(s1.x + s1.y, 0.f);
            }
            // split/exchange stages: 16 -> 8 -> 4 -> 2 -> 1
            #pragma unroll
            for (int k = 0; k < 8; k++) {
                const float snd = (lane & 16) ? gq[k] : gq[k + 8];
                const float kp  = (lane & 16) ? gq[k + 8] : gq[k];
                gq[k] = kp + __shfl_xor_sync(0xffffffffu, snd, 16);
            }
            #pragma unroll
            for (int k = 0; k < 4; k++) {
                const float snd = (lane & 8) ? gq[k] : gq[k + 4];
                const float kp  = (lane & 8) ? gq[k + 4] : gq[k];
                gq[k] = kp + __shfl_xor_sync(0xffffffffu, snd, 8);
            }
            #pragma unroll
            for (int k = 0; k < 2; k++) {
                const float snd = (lane & 4) ? gq[k] : gq[k + 2];
                const float kp  = (lane & 4) ? gq[k + 2] : gq[k];
                gq[k] = kp + __shfl_xor_sync(0xffffffffu, snd, 4);
            }
            {
                const float snd = (lane & 2) ? gq[0] : gq[1];
                const float kp  = (lane & 2) ? gq[1] : gq[0];
                gq[0] = kp + __shfl_xor_sync(0xffffffffu, snd, 2);
            }
            const float tot = gq[0] + __shfl_xor_sync(0xffffffffu, gq[0], 1);
            if ((lane & 1) == 0) gred[wid][base + ((lane >> 1) & 15)] = tot;
        }

        // ---- stage next ray's density L1 linearization into the other buffer ----
        // (ordered before next iteration's reads by the __syncthreads below)
        {
            const int nray = ray + gridDim.x;
            if (tid < 64 && nray < NRAYS) {
                const float nox = rays_o[nray * 3 + 0], noy = rays_o[nray * 3 + 1], noz = rays_o[nray * 3 + 2];
                const float ndx = rays_d[nray * 3 + 0], ndy = rays_d[nray * 3 + 1], ndz = rays_d[nray * 3 + 2];
                const float4 w1 = *reinterpret_cast<const float4*>(&sw[O_WD1T + 4 * tid]);
                const float A = fmaf(w1.x, nox, fmaf(w1.y, noy, fmaf(w1.z, noz, w1.w)));
                const float B = fmaf(w1.x, ndx, fmaf(w1.y, ndy, w1.z * ndz));
                float4 v4; v4.x = A; v4.y = A; v4.z = B; v4.w = B;
                *reinterpret_cast<float4*>(&sab[par ^ 1][4 * tid]) = v4;
            }
        }
        __syncthreads();
        if (tid < 64) gsm[tid] = gred[0][tid] + gred[1][tid] + gred[2][tid] + gred[3][tid];
        if (tid < 9) finals[tid] = red[0][tid] + red[1][tid] + red[2][tid] + red[3][tid];
        __syncthreads();

        // ---- per-ray epilogue ----
        const float wsum = finals[0];
        if (tid < 32) {
            float acc = wsum * sw[O_BK2 + tid];
            #pragma unroll 8
            for (int h = 0; h < 64; h++) acc = fmaf(gsm[h], sw[O_WK2 + h * 32 + tid], acc);
            out[OUT_CLP + (long)ray * 32 + tid] = acc;
        } else if (tid < 35) {
            const int k = tid - 32;
            out[OUT_IMG + ray * 3 + k] = finals[6 + k] + (1.f - wsum);
        } else if (tid == 35) {
            out[OUT_DEP + ray] = finals[1] * frcp(dnorm[ray]);
        } else if (tid == 36) {
            const float idn = frcp(dnorm[ray]);
            const float D = finals[1] * idn;
            out[OUT_VAR + ray] = wsum * D * D - 2.f * D * D + finals[2] * idn * idn;
        } else if (tid < 40) {
            const int k = tid - 37;
            out[OUT_CRD + ray * 3 + k] = finals[3 + k];
        }
        // next iteration's barriers protect smem reuse
    }
}

extern "C" void kernel_launch(void* const* d_in, const int* in_sizes, int n_in,
                              void* d_out, int out_size) {
    (void)in_sizes; (void)n_in; (void)out_size;
    nerf_kernel<<<NBLK, NTH>>>(
        (const float*)d_in[0],  // rays_o
        (const float*)d_in[1],  // rays_d
        (const float*)d_in[2],  // direction_norms
        (const float*)d_in[3],  (const float*)d_in[4],   // Wd1, bd1
        (const float*)d_in[5],  (const float*)d_in[6],   // Wd2, bd2
        (const float*)d_in[7],  (const float*)d_in[8],   // Wc1, bc1
        (const float*)d_in[9],  (const float*)d_in[10],  // Wc2, bc2
        (const float*)d_in[11], (const float*)d_in[12],  // Wk1, bk1
        (const float*)d_in[13], (const float*)d_in[14],  // Wk2, bk2
        (float*)d_out);
}

// round 16
// speedup vs baseline: 1.6235x; 1.6235x over previous
#include <cuda_runtime.h>
#include <math.h>

#define NRAYS 8192
#define TS 256
#define NBLK 2368
#define NTH 128

typedef unsigned long long ull;

__device__ __forceinline__ ull fma2(ull a, ull b, ull c) {
    ull d;
    asm("fma.rn.f32x2 %0, %1, %2, %3;" : "=l"(d) : "l"(a), "l"(b), "l"(c));
    return d;
}
__device__ __forceinline__ ull pack2(float lo, float hi) {
    ull d;
    asm("mov.b64 %0, {%1, %2};" : "=l"(d) : "f"(lo), "f"(hi));
    return d;
}
__device__ __forceinline__ float2 unpack2(ull v) {
    float2 r;
    asm("mov.b64 {%0, %1}, %2;" : "=f"(r.x), "=f"(r.y) : "l"(v));
    return r;
}
__device__ __forceinline__ float frcp(float x) {
    float r;
    asm("rcp.approx.f32 %0, %1;" : "=f"(r) : "f"(x));
    return r;
}
__device__ __forceinline__ float fsig(float x) {
    return frcp(1.f + __expf(-x));
}

// ---- shared weight buffer layout (float offsets, all 16B-aligned bases) ----
#define O_WD1T 0      // [64][4]  (wx,wy,wz,bias)
#define O_WD2P 256    // [64][16] cols rotated by 1: slot j = orig col (j+1)&15
#define O_BD2P 1280   // [16]     rotated bd2
#define O_WC1G 1296   // [64][16] geo weights for slots d1..d15, slot15 = 0
#define O_WC2  2320   // [64][4]  64->3 padded
#define O_BC2  2576   // [4]
#define O_WK1T 2580   // [64][16] clip l1 weights (slots d1..d15, sigma)
#define O_BK1P 3604   // [64][2]  {bk1, 0} pairs
#define O_WK2  3732   // [64][32]
#define O_BK2  5780   // [32]
#define SW_TOTAL 5812

// output layout: image[N,3] | depth[N] | depth_var[N] | coords[N,3] | rgbs[N,T,3] | clip[N,32]
#define OUT_IMG 0
#define OUT_DEP (3*NRAYS)
#define OUT_VAR (4*NRAYS)
#define OUT_CRD (5*NRAYS)
#define OUT_RGB (8*NRAYS)
#define OUT_CLP (8L*NRAYS + 3L*NRAYS*TS)

__global__ void __launch_bounds__(128) nerf_kernel(
    const float* __restrict__ rays_o,
    const float* __restrict__ rays_d,
    const float* __restrict__ dnorm,
    const float* __restrict__ Wd1, const float* __restrict__ bd1,
    const float* __restrict__ Wd2, const float* __restrict__ bd2,
    const float* __restrict__ Wc1, const float* __restrict__ bc1,
    const float* __restrict__ Wc2, const float* __restrict__ bc2,
    const float* __restrict__ Wk1, const float* __restrict__ bk1,
    const float* __restrict__ Wk2, const float* __restrict__ bk2,
    float* __restrict__ out)
{
    __shared__ __align__(16) float sw[SW_TOTAL];
    __shared__ __align__(16) float sab[2][256];  // ping-pong per-ray {A,A,B,B} density L1 lin.
    __shared__ __align__(16) float dircp[128];   // {dirc[h], 0} pairs (per ray)
    __shared__ float wp0[4], wp1[4];
    __shared__ float red[4][12];
    __shared__ float finals[12];
    __shared__ __align__(16) float gred[4][64];
    __shared__ __align__(16) float gsm[64];

    const int tid = threadIdx.x;
    const int lane = tid & 31;
    const int wid = tid >> 5;

    // ---- stage weights into smem ----
    for (int i = tid; i < 256; i += NTH) { int h = i >> 2, c = i & 3; sw[O_WD1T + i] = (c < 3) ? Wd1[c * 64 + h] : bd1[h]; }
    for (int i = tid; i < 1024; i += NTH) { int j = i & 15; sw[O_WD2P + i] = Wd2[(i & ~15) + ((j + 1) & 15)]; }
    for (int i = tid; i < 16; i += NTH) sw[O_BD2P + i] = bd2[(i + 1) & 15];
    for (int i = tid; i < 1024; i += NTH) { int h = i >> 4, c = i & 15; sw[O_WC1G + i] = (c < 15) ? Wc1[(3 + c) * 64 + h] : 0.f; }
    for (int i = tid; i < 256; i += NTH) { int h = i >> 2, k = i & 3; sw[O_WC2 + i] = (k < 3) ? Wc2[h * 3 + k] : 0.f; }
    if (tid < 4) sw[O_BC2 + tid] = (tid < 3) ? bc2[tid] : 0.f;
    for (int i = tid; i < 1024; i += NTH) { int h = i >> 4, c = i & 15; sw[O_WK1T + i] = Wk1[c * 64 + h]; }
    for (int i = tid; i < 128; i += NTH) sw[O_BK1P + i] = (i & 1) ? 0.f : bk1[i >> 1];
    for (int i = tid; i < 2048; i += NTH) sw[O_WK2 + i] = Wk2[i];
    for (int i = tid; i < 32; i += NTH) sw[O_BK2 + i] = bk2[i];
    __syncthreads();

    // ---- pre-stage density L1 linearization for the first ray ----
    if (tid < 64 && blockIdx.x < NRAYS) {
        const int r0 = blockIdx.x;
        const float nox = rays_o[r0 * 3 + 0], noy = rays_o[r0 * 3 + 1], noz = rays_o[r0 * 3 + 2];
        const float ndx = rays_d[r0 * 3 + 0], ndy = rays_d[r0 * 3 + 1], ndz = rays_d[r0 * 3 + 2];
        const float4 w1 = *reinterpret_cast<const float4*>(&sw[O_WD1T + 4 * tid]);
        const float A = fmaf(w1.x, nox, fmaf(w1.y, noy, fmaf(w1.z, noz, w1.w)));
        const float B = fmaf(w1.x, ndx, fmaf(w1.y, ndy, w1.z * ndz));
        float4 v4; v4.x = A; v4.y = A; v4.z = B; v4.w = B;
        *reinterpret_cast<float4*>(&sab[0][4 * tid]) = v4;
    }
    __syncthreads();

    int par = 0;
    for (int ray = blockIdx.x; ray < NRAYS; ray += gridDim.x, par ^= 1) {
        // ---- ray setup ----
        const float ox = rays_o[ray * 3 + 0], oy = rays_o[ray * 3 + 1], oz = rays_o[ray * 3 + 2];
        const float dx = rays_d[ray * 3 + 0], dy = rays_d[ray * 3 + 1], dz = rays_d[ray * 3 + 2];

        // per-ray direction contribution to color layer-1 (incl. bias), stored as {v,0} pairs
        // (scan __syncthreads below orders these writes before the color-loop reads)
        if (tid < 64) {
            dircp[2 * tid] = bc1[tid] + dx * Wc1[tid] + dy * Wc1[64 + tid] + dz * Wc1[128 + tid];
            dircp[2 * tid + 1] = 0.f;
        }

        const float ix = frcp(dx), iy = frcp(dy), iz = frcp(dz);
        float t1, t2;
        t1 = (-1.f - ox) * ix; t2 = (1.f - ox) * ix;
        float mnx = fminf(t1, t2), mxx = fmaxf(t1, t2);
        t1 = (-1.f - oy) * iy; t2 = (1.f - oy) * iy;
        float mny = fminf(t1, t2), mxy = fmaxf(t1, t2);
        t1 = (-1.f - oz) * iz; t2 = (1.f - oz) * iz;
        float mnz = fminf(t1, t2), mxz = fmaxf(t1, t2);
        const float nearv = fmaxf(fmaxf(fmaxf(mnx, mny), mnz), 0.2f);
        const float farv  = fmaxf(fminf(fminf(mxx, mxy), mxz), nearv + 0.0001f);
        const float span = farv - nearv;

        const float tstep = span * (1.f / (TS - 1));
        const float zv0 = nearv + tstep * (float)tid;
        const float zv1 = nearv + tstep * (float)(tid + 128);
        const ull zp = pack2(zv0, zv1);

        // ---- density MLP: linearized L1 (1 FMA2 per h) -> relu -> 16 (permuted, packed) ----
        // accumulator pairs: (d1,d2),(d3,d4),...,(d13,d14),(d15,d0)
        ull acc0[8], acc1[8];
        {
            const ull* bp = reinterpret_cast<const ull*>(&sw[O_BD2P]);
            #pragma unroll
            for (int j = 0; j < 8; j++) { acc0[j] = bp[j]; acc1[j] = bp[j]; }
        }
        {
            const float* sabp = sab[par];
            #pragma unroll 8
            for (int h = 0; h < 64; h++) {
                const ulonglong2 ab = *reinterpret_cast<const ulonglong2*>(&sabp[4 * h]);
                const float2 pp = unpack2(fma2(zp, ab.y, ab.x));   // {A+B*zv0, A+B*zv1}
                const float p0 = fmaxf(pp.x, 0.f);
                const float p1 = fmaxf(pp.y, 0.f);
                const ull p0b = pack2(p0, p0);
                const ull p1b = pack2(p1, p1);
                const ulonglong2* wr = reinterpret_cast<const ulonglong2*>(&sw[O_WD2P + h * 16]);
                #pragma unroll
                for (int q = 0; q < 4; q++) {
                    const ulonglong2 w = wr[q];
                    acc0[2 * q + 0] = fma2(p0b, w.x, acc0[2 * q + 0]);
                    acc0[2 * q + 1] = fma2(p0b, w.y, acc0[2 * q + 1]);
                    acc1[2 * q + 0] = fma2(p1b, w.x, acc1[2 * q + 0]);
                    acc1[2 * q + 1] = fma2(p1b, w.y, acc1[2 * q + 1]);
                }
            }
        }
        const float2 t7a = unpack2(acc0[7]);   // (d15, d0)
        const float2 t7b = unpack2(acc1[7]);
        const float sigma0 = __expf(t7a.y);
        const float sigma1 = __expf(t7b.y);

        // ---- alpha + two-level transmittance scan over 256 samples ----
        const float delta1 = (tid < 127) ? tstep : span * (1.f / TS);
        const float alpha0 = 1.f - __expf(-tstep * sigma0);
        const float alpha1 = 1.f - __expf(-delta1 * sigma1);
        float v0 = 1.f - alpha0 + 1e-15f;
        float v1 = 1.f - alpha1 + 1e-15f;
        #pragma unroll
        for (int off = 1; off < 32; off <<= 1) {
            const float n0 = __shfl_up_sync(0xffffffffu, v0, off);
            const float n1 = __shfl_up_sync(0xffffffffu, v1, off);
            if (lane >= off) { v0 *= n0; v1 *= n1; }
        }
        if (lane == 31) { wp0[wid] = v0; wp1[wid] = v1; }
        __syncthreads();
        float pre0p = 1.f, pre1p;
        {
            #pragma unroll
            for (int i = 0; i < 4; i++) if (i < wid) pre0p *= wp0[i];
            const float all0 = wp0[0] * wp0[1] * wp0[2] * wp0[3];
            pre1p = all0;
            #pragma unroll
            for (int i = 0; i < 4; i++) if (i < wid) pre1p *= wp1[i];
        }
        float e0 = __shfl_up_sync(0xffffffffu, v0, 1);
        float e1 = __shfl_up_sync(0xffffffffu, v1, 1);
        if (lane == 0) { e0 = 1.f; e1 = 1.f; }
        float w0v = alpha0 * (pre0p * e0);
        float w1v = alpha1 * (pre1p * e1);
        const bool m0 = (w0v > 0.0001f);
        const bool m1 = (w1v > 0.0001f);
        if (!m0) w0v = 0.f;
        if (!m1) w1v = 0.f;

        // ---- color MLP: [dir(hoisted), geo(15)] -> 64 (relu) -> 3 (sigmoid) ----
        float c00 = sw[O_BC2 + 0], c01 = sw[O_BC2 + 1], c02 = sw[O_BC2 + 2];
        float c10 = c00, c11 = c01, c12 = c02;
        #pragma unroll 2
        for (int h = 0; h < 64; h++) {
            ull a0 = *reinterpret_cast<const ull*>(&dircp[2 * h]);
            ull a1 = a0;
            const ulonglong2* wr = reinterpret_cast<const ulonglong2*>(&sw[O_WC1G + h * 16]);
            #pragma unroll
            for (int q = 0; q < 4; q++) {
                const ulonglong2 w = wr[q];
                a0 = fma2(acc0[2 * q + 0], w.x, a0);
                a0 = fma2(acc0[2 * q + 1], w.y, a0);
                a1 = fma2(acc1[2 * q + 0], w.x, a1);
                a1 = fma2(acc1[2 * q + 1], w.y, a1);
            }
            const float2 s0 = unpack2(a0);
            const float2 s1 = unpack2(a1);
            const float hv0 = fmaxf(s0.x + s0.y, 0.f);
            const float hv1 = fmaxf(s1.x + s1.y, 0.f);
            const float4 w2 = *reinterpret_cast<const float4*>(&sw[O_WC2 + h * 4]);
            c00 = fmaf(hv0, w2.x, c00); c01 = fmaf(hv0, w2.y, c01); c02 = fmaf(hv0, w2.z, c02);
            c10 = fmaf(hv1, w2.x, c10); c11 = fmaf(hv1, w2.y, c11); c12 = fmaf(hv1, w2.z, c12);
        }
        float r00 = fsig(c00), r01 = fsig(c01), r02 = fsig(c02);
        float r10 = fsig(c10), r11 = fsig(c11), r12 = fsig(c12);
        if (!m0) { r00 = 0.f; r01 = 0.f; r02 = 0.f; }
        if (!m1) { r10 = 0.f; r11 = 0.f; r12 = 0.f; }
        {
            const long b0 = OUT_RGB + ((long)ray * TS + tid) * 3;
            out[b0 + 0] = r00; out[b0 + 1] = r01; out[b0 + 2] = r02;
            const long b1 = OUT_RGB + ((long)ray * TS + tid + 128) * 3;
            out[b1 + 0] = r10; out[b1 + 1] = r11; out[b1 + 2] = r12;
        }

        // ---- 9-quantity block reduction (positions computed here) ----
        {
            const float px0 = fminf(fmaxf(fmaf(dx, zv0, ox), -1.f), 1.f);
            const float py0 = fminf(fmaxf(fmaf(dy, zv0, oy), -1.f), 1.f);
            const float pz0 = fminf(fmaxf(fmaf(dz, zv0, oz), -1.f), 1.f);
            const float px1 = fminf(fmaxf(fmaf(dx, zv1, ox), -1.f), 1.f);
            const float py1 = fminf(fmaxf(fmaf(dy, zv1, oy), -1.f), 1.f);
            const float pz1 = fminf(fmaxf(fmaf(dz, zv1, oz), -1.f), 1.f);
            float vals[9];
            vals[0] = w0v + w1v;
            vals[1] = w0v * zv0 + w1v * zv1;
            vals[2] = w0v * zv0 * zv0 + w1v * zv1 * zv1;
            vals[3] = w0v * px0 + w1v * px1;
            vals[4] = w0v * py0 + w1v * py1;
            vals[5] = w0v * pz0 + w1v * pz1;
            vals[6] = w0v * r00 + w1v * r10;
            vals[7] = w0v * r01 + w1v * r11;
            vals[8] = w0v * r02 + w1v * r12;
            #pragma unroll
            for (int q = 0; q < 9; q++) {
                float x = vals[q];
                #pragma unroll
                for (int off = 16; off > 0; off >>= 1) x += __shfl_xor_sync(0xffffffffu, x, off);
                vals[q] = x;
            }
            if (lane == 0) {
                #pragma unroll
                for (int q = 0; q < 9; q++) red[wid][q] = vals[q];
            }
        }

        // ---- clip hidden layer: [geo(15), sigma] -> 64 (relu), weighted-reduced over t ----
        // butterfly transpose-reduction: 16 h's per pass, 4 passes
        const ull kp0 = pack2(t7a.x, sigma0);   // (d15, sigma)
        const ull kp1 = pack2(t7b.x, sigma1);
        #pragma unroll 1
        for (int base = 0; base < 64; base += 16) {
            float gq[16];
            #pragma unroll
            for (int j = 0; j < 16; j++) {
                const int h = base + j;
                ull a0 = *reinterpret_cast<const ull*>(&sw[O_BK1P + 2 * h]);
                ull a1 = a0;
                const ulonglong2* wr = reinterpret_cast<const ulonglong2*>(&sw[O_WK1T + h * 16]);
                #pragma unroll
                for (int q = 0; q < 3; q++) {
                    const ulonglong2 w = wr[q];
                    a0 = fma2(acc0[2 * q + 0], w.x, a0);
                    a0 = fma2(acc0[2 * q + 1], w.y, a0);
                    a1 = fma2(acc1[2 * q + 0], w.x, a1);
                    a1 = fma2(acc1[2 * q + 1], w.y, a1);
                }
                const ulonglong2 w3 = wr[3];
                a0 = fma2(acc0[6], w3.x, a0);
                a1 = fma2(acc1[6], w3.x, a1);
                a0 = fma2(kp0, w3.y, a0);
                a1 = fma2(kp1, w3.y, a1);
                const float2 s0 = unpack2(a0);
                const float2 s1 = unpack2(a1);
                gq[j] = w0v * fmaxf(s0.x + s0.y, 0.f) + w1v * fmaxf(s1.x + s1.y, 0.f);
            }
            // split/exchange stages: 16 -> 8 -> 4 -> 2 -> 1
            #pragma unroll
            for (int k = 0; k < 8; k++) {
                const float snd = (lane & 16) ? gq[k] : gq[k + 8];
                const float kp  = (lane & 16) ? gq[k + 8] : gq[k];
                gq[k] = kp + __shfl_xor_sync(0xffffffffu, snd, 16);
            }
            #pragma unroll
            for (int k = 0; k < 4; k++) {
                const float snd = (lane & 8) ? gq[k] : gq[k + 4];
                const float kp  = (lane & 8) ? gq[k + 4] : gq[k];
                gq[k] = kp + __shfl_xor_sync(0xffffffffu, snd, 8);
            }
            #pragma unroll
            for (int k = 0; k < 2; k++) {
                const float snd = (lane & 4) ? gq[k] : gq[k + 2];
                const float kp  = (lane & 4) ? gq[k + 2] : gq[k];
                gq[k] = kp + __shfl_xor_sync(0xffffffffu, snd, 4);
            }
            {
                const float snd = (lane & 2) ? gq[0] : gq[1];
                const float kp  = (lane & 2) ? gq[1] : gq[0];
                gq[0] = kp + __shfl_xor_sync(0xffffffffu, snd, 2);
            }
            const float tot = gq[0] + __shfl_xor_sync(0xffffffffu, gq[0], 1);
            if ((lane & 1) == 0) gred[wid][base + ((lane >> 1) & 15)] = tot;
        }

        // ---- stage next ray's density L1 linearization into the other buffer ----
        // (ordered before next iteration's reads by the __syncthreads below)
        {
            const int nray = ray + gridDim.x;
            if (tid < 64 && nray < NRAYS) {
                const float nox = rays_o[nray * 3 + 0], noy = rays_o[nray * 3 + 1], noz = rays_o[nray * 3 + 2];
                const float ndx = rays_d[nray * 3 + 0], ndy = rays_d[nray * 3 + 1], ndz = rays_d[nray * 3 + 2];
                const float4 w1 = *reinterpret_cast<const float4*>(&sw[O_WD1T + 4 * tid]);
                const float A = fmaf(w1.x, nox, fmaf(w1.y, noy, fmaf(w1.z, noz, w1.w)));
                const float B = fmaf(w1.x, ndx, fmaf(w1.y, ndy, w1.z * ndz));
                float4 v4; v4.x = A; v4.y = A; v4.z = B; v4.w = B;
                *reinterpret_cast<float4*>(&sab[par ^ 1][4 * tid]) = v4;
            }
        }
        __syncthreads();
        if (tid < 64) gsm[tid] = gred[0][tid] + gred[1][tid] + gred[2][tid] + gred[3][tid];
        if (tid < 9) finals[tid] = red[0][tid] + red[1][tid] + red[2][tid] + red[3][tid];
        __syncthreads();

        // ---- per-ray epilogue ----
        const float wsum = finals[0];
        if (tid < 32) {
            float acc = wsum * sw[O_BK2 + tid];
            #pragma unroll 8
            for (int h = 0; h < 64; h++) acc = fmaf(gsm[h], sw[O_WK2 + h * 32 + tid], acc);
            out[OUT_CLP + (long)ray * 32 + tid] = acc;
        } else if (tid < 35) {
            const int k = tid - 32;
            out[OUT_IMG + ray * 3 + k] = finals[6 + k] + (1.f - wsum);
        } else if (tid == 35) {
            out[OUT_DEP + ray] = finals[1] * frcp(dnorm[ray]);
        } else if (tid == 36) {
            const float idn = frcp(dnorm[ray]);
            const float D = finals[1] * idn;
            out[OUT_VAR + ray] = wsum * D * D - 2.f * D * D + finals[2] * idn * idn;
        } else if (tid < 40) {
            const int k = tid - 37;
            out[OUT_CRD + ray * 3 + k] = finals[3 + k];
        }
        // next iteration's barriers protect smem reuse
    }
}

extern "C" void kernel_launch(void* const* d_in, const int* in_sizes, int n_in,
                              void* d_out, int out_size) {
    (void)in_sizes; (void)n_in; (void)out_size;
    nerf_kernel<<<NBLK, NTH>>>(
        (const float*)d_in[0],  // rays_o
        (const float*)d_in[1],  // rays_d
        (const float*)d_in[2],  // direction_norms
        (const float*)d_in[3],  (const float*)d_in[4],   // Wd1, bd1
        (const float*)d_in[5],  (const float*)d_in[6],   // Wd2, bd2
        (const float*)d_in[7],  (const float*)d_in[8],   // Wc1, bc1
        (const float*)d_in[9],  (const float*)d_in[10],  // Wc2, bc2
        (const float*)d_in[11], (const float*)d_in[12],  // Wk1, bk1
        (const float*)d_in[13], (const float*)d_in[14],  // Wk2, bk2
        (float*)d_out);
}